// round 17
// baseline (speedup 1.0000x reference)
#include <cuda_runtime.h>
#include <cuda_bf16.h>
#include <cstdint>

// Problem constants: T=2048, N=64, D=1024
#define T_DIM 2048
#define N_DIM 64
#define D_VEC 256                 // float4 per row
#define VEC_PER_LANE 8            // 256 / 32 lanes
#define NWARPS 4
#define NTHREADS 128
#define NBX 32                    // 32 blocks * 4 warps = 128 streams per sequence
#define NSTREAMS 128              // rows t = s + 128*k belong to stream s
#define NSTAGES 2
#define HALF_LOG_2PI 0.91893853320467274178f
#define EPS_VAR 1e-6f

__device__ __forceinline__ void cp_async16(unsigned int saddr, const void* gptr) {
    asm volatile("cp.async.cg.shared.global [%0], [%1], 16;\n"
                 :: "r"(saddr), "l"(gptr));
}
__device__ __forceinline__ void cp_commit() {
    asm volatile("cp.async.commit_group;\n" ::: "memory");
}
__device__ __forceinline__ void cp_wait1() {
    asm volatile("cp.async.wait_group 1;\n" ::: "memory");
}

// 5 blocks/SM (regs<=102 target, smem 5x33KB=165KB < 228KB): 20 streams/SM.
__global__ __launch_bounds__(NTHREADS, 5)
void gnll_kernel(const float* __restrict__ y,     // (T, N)
                 const float4* __restrict__ x4,   // (T, N, D/4)
                 const float4* __restrict__ W4,   // (2, D/4)
                 const int* __restrict__ lens,    // (N,)
                 float* __restrict__ out)         // (N,)
{
    // Per-warp private double buffer: 2 stages x 4KB per warp. No block sync.
    __shared__ float4 buf[NWARPS][NSTAGES][D_VEC];

    const int n    = blockIdx.y;
    const int bx   = blockIdx.x;
    const int len  = lens[n];
    const int tid  = threadIdx.x;
    const int wid  = tid >> 5;
    const int lane = tid & 31;

    // Warp-private stream: rows t = s + 128*k, all strictly < len by kmax.
    const int s = bx * NWARPS + wid;               // 0..127, warp-uniform
    const int kmax = (len > s) ? ((len - s + NSTREAMS - 1) >> 7) : 0;
    if (kmax == 0) return;                         // warp-uniform exit

    // Preload W lane-striped into registers (64 regs).
    float4 w0[VEC_PER_LANE], w1[VEC_PER_LANE];
    #pragma unroll
    for (int i = 0; i < VEC_PER_LANE; i++) {
        w0[i] = W4[i * 32 + lane];
        w1[i] = W4[D_VEC + i * 32 + lane];
    }

    // Issue one full row (4KB) into this warp's stage st; one commit per call.
    // Lane l writes slots {c*32+l}; it later reads exactly those slots, so
    // per-thread wait_group suffices — no __syncwarp needed.
    auto issue = [&](int k, int st) {
        const int t = s + (k << 7);
        const float4* g = x4 + ((size_t)t * N_DIM + n) * D_VEC + lane;
        unsigned int sb = (unsigned int)__cvta_generic_to_shared(&buf[wid][st][lane]);
        #pragma unroll
        for (int c = 0; c < VEC_PER_LANE; c++)
            cp_async16(sb + (unsigned int)c * 32u * 16u, g + c * 32);
        cp_commit();
    };

    // Prologue: always exactly NSTAGES commits.
    issue(0, 0);
    if (kmax > 1) issue(1, 1); else cp_commit();

    float warp_sum = 0.0f;

    // y software-pipelined one tile ahead: y for tile k is in flight a full
    // tile period (~1900 cyc) before use.
    float yv_next = __ldg(y + (size_t)s * N_DIM + n);

    for (int k = 0; k < kmax; k++) {
        const float yv = yv_next;
        if (k + 1 < kmax)
            yv_next = __ldg(y + (size_t)(s + ((k + 1) << 7)) * N_DIM + n);

        cp_wait1();                          // tile k's group complete
        const int st = k & 1;
        const float4* src = &buf[wid][st][0];

        // Split accumulators: 2 chains of 16 dependent FMAs per output
        // (instead of 1x32) -> per-tile critical path ~halves.
        float a0e = 0.0f, a0o = 0.0f, a1e = 0.0f, a1o = 0.0f;
        #pragma unroll
        for (int i = 0; i < VEC_PER_LANE; i += 2) {
            float4 v0 = src[i * 32 + lane];
            float4 v1 = src[(i + 1) * 32 + lane];
            a0e = fmaf(v0.x, w0[i].x, a0e);
            a0e = fmaf(v0.y, w0[i].y, a0e);
            a0e = fmaf(v0.z, w0[i].z, a0e);
            a0e = fmaf(v0.w, w0[i].w, a0e);
            a1e = fmaf(v0.x, w1[i].x, a1e);
            a1e = fmaf(v0.y, w1[i].y, a1e);
            a1e = fmaf(v0.z, w1[i].z, a1e);
            a1e = fmaf(v0.w, w1[i].w, a1e);
            a0o = fmaf(v1.x, w0[i + 1].x, a0o);
            a0o = fmaf(v1.y, w0[i + 1].y, a0o);
            a0o = fmaf(v1.z, w0[i + 1].z, a0o);
            a0o = fmaf(v1.w, w0[i + 1].w, a0o);
            a1o = fmaf(v1.x, w1[i + 1].x, a1o);
            a1o = fmaf(v1.y, w1[i + 1].y, a1o);
            a1o = fmaf(v1.z, w1[i + 1].z, a1o);
            a1o = fmaf(v1.w, w1[i + 1].w, a1o);
        }

        // Refill the consumed stage immediately (before the reduce chain) so
        // the next tile's DRAM fetch overlaps the shuffle latency.
        if (k + NSTAGES < kmax) issue(k + NSTAGES, st); else cp_commit();

        float a0 = a0e + a0o;
        float a1 = a1e + a1o;
        #pragma unroll
        for (int off = 16; off > 0; off >>= 1) {
            a0 += __shfl_xor_sync(0xFFFFFFFFu, a0, off);
            a1 += __shfl_xor_sync(0xFFFFFFFFu, a1, off);
        }
        if (lane == 0) {
            float mu  = a0;
            float var = fmaxf(1.0f / (1.0f + __expf(-a1)), EPS_VAR);
            float d   = yv - mu;
            warp_sum += 0.5f * (__logf(var) + d * d / var) + HALF_LOG_2PI;
        }
    }

    if (lane == 0) atomicAdd(&out[n], warp_sum);
}

extern "C" void kernel_launch(void* const* d_in, const int* in_sizes, int n_in,
                              void* d_out, int out_size) {
    // metadata order: y (T*N f32), x (T*N*D f32), W (2*D f32), lens (N i32)
    const float*  y    = (const float*)d_in[0];
    const float4* x4   = (const float4*)d_in[1];
    const float4* W4   = (const float4*)d_in[2];
    const int*    lens = (const int*)d_in[3];
    float*        out  = (float*)d_out;

    // Zero the accumulator via a memset node (cheaper than a kernel node;
    // graph-capturable, no allocation). 0x00 bit pattern == 0.0f.
    cudaMemsetAsync(out, 0, N_DIM * sizeof(float));

    dim3 grid(NBX, N_DIM);
    dim3 block(NTHREADS);
    gnll_kernel<<<grid, block>>>(y, x4, W4, lens, out);
}